// round 9
// baseline (speedup 1.0000x reference)
#include <cuda_runtime.h>
#include <math.h>

#define T_SEQ 8192
#define HDIM  1024
#define NBLK  128     // scan CTAs (<=148 SMs -> all co-resident at 1 CTA/SM)

typedef unsigned long long u64;

// ---------------- static device scratch (no runtime allocation) ----------------
__device__ float g_XP[3][T_SEQ * HDIM];              // xu, xr, xc projections
__device__ __align__(16) float g_h[2][HDIM];         // double-buffered hidden state
__device__ __align__(16) u64 g_flag[NBLK];           // per-CTA monotonic step flags

// ---------------- per-launch reset (graph-replay safe) ----------------
__global__ void reset_kernel() {
    int i = threadIdx.x;
    for (int k = i; k < HDIM; k += 256) {
        g_h[0][k] = 0.f;      // h_0 = 0
        g_h[1][k] = 0.f;
    }
    if (i < NBLK) g_flag[i] = 0ULL;
}

// ---------------- Phase 1: C[z] = x @ U[z]^T + bias[z]  (fp32, NT) ----------------
__global__ __launch_bounds__(256) void proj_gemm(
    const float* __restrict__ x,
    const float* __restrict__ Uu, const float* __restrict__ Ur, const float* __restrict__ Uc,
    const float* __restrict__ Bu, const float* __restrict__ Br, const float* __restrict__ Bc)
{
    const int z = blockIdx.z;
    const float* __restrict__ Bmat = (z == 0) ? Uu : ((z == 1) ? Ur : Uc);
    const float* __restrict__ bias = (z == 0) ? Bu : ((z == 1) ? Br : Bc);
    float* __restrict__ C = g_XP[z];

    const int m0 = blockIdx.x * 128;
    const int n0 = blockIdx.y * 64;

    __shared__ __align__(16) float As[16][132];
    __shared__ __align__(16) float Bs[16][68];

    const int tid = threadIdx.x;
    const int tx  = tid & 15;
    const int ty  = tid >> 4;

    float acc[8][4];
#pragma unroll
    for (int i = 0; i < 8; i++)
#pragma unroll
        for (int j = 0; j < 4; j++) acc[i][j] = 0.f;

    for (int k0 = 0; k0 < HDIM; k0 += 16) {
#pragma unroll
        for (int i = 0; i < 2; i++) {
            int idx = tid * 2 + i;
            int row = idx >> 2;
            int c4  = idx & 3;
            float4 v = *reinterpret_cast<const float4*>(x + (size_t)(m0 + row) * HDIM + k0 + c4 * 4);
            As[c4 * 4 + 0][row] = v.x;
            As[c4 * 4 + 1][row] = v.y;
            As[c4 * 4 + 2][row] = v.z;
            As[c4 * 4 + 3][row] = v.w;
        }
        {
            int row = tid >> 2;
            int c4  = tid & 3;
            float4 v = *reinterpret_cast<const float4*>(Bmat + (size_t)(n0 + row) * HDIM + k0 + c4 * 4);
            Bs[c4 * 4 + 0][row] = v.x;
            Bs[c4 * 4 + 1][row] = v.y;
            Bs[c4 * 4 + 2][row] = v.z;
            Bs[c4 * 4 + 3][row] = v.w;
        }
        __syncthreads();

#pragma unroll
        for (int k = 0; k < 16; k++) {
            float a[8], b[4];
#pragma unroll
            for (int i = 0; i < 8; i++) a[i] = As[k][ty * 8 + i];
#pragma unroll
            for (int j = 0; j < 4; j++) b[j] = Bs[k][tx * 4 + j];
#pragma unroll
            for (int i = 0; i < 8; i++)
#pragma unroll
                for (int j = 0; j < 4; j++) acc[i][j] = fmaf(a[i], b[j], acc[i][j]);
        }
        __syncthreads();
    }

    float4 bv = *reinterpret_cast<const float4*>(bias + n0 + tx * 4);
#pragma unroll
    for (int i = 0; i < 8; i++) {
        float4 o;
        o.x = acc[i][0] + bv.x;
        o.y = acc[i][1] + bv.y;
        o.z = acc[i][2] + bv.z;
        o.w = acc[i][3] + bv.w;
        *reinterpret_cast<float4*>(C + (size_t)(m0 + ty * 8 + i) * HDIM + n0 + tx * 4) = o;
    }
}

// ---------------- Phase 2: persistent scan, hierarchical flag sync ----------------
__device__ __forceinline__ float sigmoidf_(float v) {
    return 1.f / (1.f + __expf(-v));
}
__device__ __forceinline__ u64 ld_rlx64(const u64* p) {
    u64 v;
    asm volatile("ld.relaxed.gpu.global.u64 %0, [%1];" : "=l"(v) : "l"(p) : "memory");
    return v;
}
__device__ __forceinline__ float ld_rlx32f(const float* p) {
    unsigned v;
    asm volatile("ld.relaxed.gpu.global.b32 %0, [%1];" : "=r"(v) : "l"(p) : "memory");
    return __uint_as_float(v);
}
__device__ __forceinline__ void st_rlx32f(float* p, float v) {
    asm volatile("st.relaxed.gpu.global.b32 [%0], %1;" :: "l"(p), "r"(__float_as_uint(v)) : "memory");
}
__device__ __forceinline__ void st_rel64(u64* p, u64 v) {
    asm volatile("st.release.gpu.global.u64 [%0], %1;" :: "l"(p), "l"(v) : "memory");
}
__device__ __forceinline__ void fence_acqrel() {
    asm volatile("fence.acq_rel.gpu;" ::: "memory");
}

__global__ __launch_bounds__(256, 1) void scan_kernel(
    const float* __restrict__ Wu, const float* __restrict__ Wr, const float* __restrict__ Wc,
    float* __restrict__ out)   // out[0:1024] = h_final, out[1024 + t*1024 + r] = outputs
{
    __shared__ __align__(16) float hs[HDIM];

    const int tid = threadIdx.x;
    const int l   = tid & 31;
    const int w   = tid >> 5;
    const int r   = blockIdx.x * 8 + w;      // this warp's hidden row

    // Scalar weight layout (proven): lane l owns columns k*32 + l.
    float wu[32], wr[32], wc[32];
#pragma unroll
    for (int k = 0; k < 32; k++) {
        int c = k * 32 + l;
        wu[k] = __ldg(Wu + (size_t)r * HDIM + c);
        wr[k] = __ldg(Wr + (size_t)r * HDIM + c);
        wc[k] = __ldg(Wc + (size_t)r * HDIM + c);
    }

    const float* __restrict__ XPu = g_XP[0];
    const float* __restrict__ XPr = g_XP[1];
    const float* __restrict__ XPc = g_XP[2];

#pragma unroll 1
    for (int t = 0; t < T_SEQ; ++t) {
        const int buf = t & 1;               // h_t lives in g_h[t&1]

        // Independent DRAM loads first: overlap with flag detection below.
        float au = 0.f, ar = 0.f, ac = 0.f;
        if (l == 0) {
            size_t off = (size_t)t * HDIM + r;
            au = __ldcg(XPu + off);
            ar = __ldcg(XPr + off);
            ac = __ldcg(XPc + off);
        }

        // Only warp 0 polls: lane l watches flags 4l..4l+3 until all >= t.
        // 128 CTAs x 32 lanes x 4 words -> ~64x less spin traffic than R5/R6.
        if (w == 0) {
            const u64* fp = g_flag + 4 * l;
            const u64 tgt = (u64)t;
            while (true) {
                u64 f0 = ld_rlx64(fp + 0);
                u64 f1 = ld_rlx64(fp + 1);
                u64 f2 = ld_rlx64(fp + 2);
                u64 f3 = ld_rlx64(fp + 3);
                if (f0 >= tgt && f1 >= tgt && f2 >= tgt && f3 >= tgt) break;
            }
            fence_acqrel();                  // acquire: flags -> h visibility
        }
        __syncthreads();                     // [A] publish detection CTA-wide

        // Stage h_t: 4 rows per thread (rows 4*tid..4*tid+3), strong loads.
        {
            const float* hb = g_h[buf] + 4 * tid;
            float4 hv;
            hv.x = ld_rlx32f(hb + 0);
            hv.y = ld_rlx32f(hb + 1);
            hv.z = ld_rlx32f(hb + 2);
            hv.w = ld_rlx32f(hb + 3);
            reinterpret_cast<float4*>(hs)[tid] = hv;
        }
        __syncthreads();                     // [B]

        // Three scalar dot products with the staged h.
        float su = 0.f, sr = 0.f, sc = 0.f;
#pragma unroll
        for (int k = 0; k < 32; k++) {
            float hval = hs[k * 32 + l];
            su = fmaf(wu[k], hval, su);
            sr = fmaf(wr[k], hval, sr);
            sc = fmaf(wc[k], hval, sc);
        }
#pragma unroll
        for (int off = 16; off > 0; off >>= 1) {
            su += __shfl_down_sync(0xffffffffu, su, off);
            sr += __shfl_down_sync(0xffffffffu, sr, off);
            sc += __shfl_down_sync(0xffffffffu, sc, off);
        }

        if (l == 0) {
            float hprev = hs[r];
            float u  = sigmoidf_(au + su);
            float rg = sigmoidf_(ar + sr);
            float cd = sigmoidf_(ac + rg * sc);
            float hn = fmaf(u, hprev - cd, cd);   // u*h + (1-u)*cand

            st_rlx32f(&g_h[(t + 1) & 1][r], hn);  // h_{t+1}, parallel addresses
            out[HDIM + (size_t)t * HDIM + r] = hn;
            if (t == T_SEQ - 1) out[r] = hn;
        }

        __syncthreads();                     // [C] all 8 rows of this CTA stored
        if (tid == 0)
            st_rel64(&g_flag[blockIdx.x], (u64)(t + 1));  // release: rows -> flag
        // Reuse safety: CTA c overwrites g_h[(t+1)&1] (= h_{t-1}) only after
        // detecting flags >= t, i.e. after every CTA d's release(t), which
        // follows d's staging reads of h_{t-1}. Acquire-fence + bar [A]
        // extend the edge to all of c's warps.
    }
}

// ---------------- launch ----------------
extern "C" void kernel_launch(void* const* d_in, const int* in_sizes, int n_in,
                              void* d_out, int out_size) {
    const float* x  = (const float*)d_in[0];
    const float* Uu = (const float*)d_in[1];
    const float* Wu = (const float*)d_in[2];
    const float* Bu = (const float*)d_in[3];
    const float* Ur = (const float*)d_in[4];
    const float* Wr = (const float*)d_in[5];
    const float* Br = (const float*)d_in[6];
    const float* Uc = (const float*)d_in[7];
    const float* Wc = (const float*)d_in[8];
    const float* Bc = (const float*)d_in[9];
    float* out = (float*)d_out;

    reset_kernel<<<1, 256>>>();

    dim3 g(T_SEQ / 128, HDIM / 64, 3);
    proj_gemm<<<g, 256>>>(x, Uu, Ur, Uc, Bu, Br, Bc);

    scan_kernel<<<NBLK, 256>>>(Wu, Wr, Wc, out);
}

// round 12
// speedup vs baseline: 3.1196x; 3.1196x over previous
#include <cuda_runtime.h>
#include <math.h>

#define T_SEQ 8192
#define HDIM  1024
#define NBLK  128     // scan CTAs (<=148 SMs -> all co-resident at 1 CTA/SM)

typedef unsigned long long u64;

// ---------------- static device scratch (no runtime allocation) ----------------
__device__ float           g_XP[3][T_SEQ * HDIM];   // xu, xr, xc projections
__device__ __align__(16) float g_hbuf[2][HDIM];     // double-buffered hidden state
__device__ unsigned        g_cnt;                   // global barrier counter

// ---------------- per-launch reset (graph-replay safe) ----------------
__global__ void reset_kernel() {
    int i = threadIdx.x;
    if (i == 0) g_cnt = 0u;
    for (int k = i; k < HDIM; k += 256) {
        g_hbuf[0][k] = 0.f;
        g_hbuf[1][k] = 0.f;
    }
}

// ---------------- Phase 1: C[z] = x @ U[z]^T + bias[z]  (fp32, NT) ----------------
__global__ __launch_bounds__(256) void proj_gemm(
    const float* __restrict__ x,
    const float* __restrict__ Uu, const float* __restrict__ Ur, const float* __restrict__ Uc,
    const float* __restrict__ Bu, const float* __restrict__ Br, const float* __restrict__ Bc)
{
    const int z = blockIdx.z;
    const float* __restrict__ Bmat = (z == 0) ? Uu : ((z == 1) ? Ur : Uc);
    const float* __restrict__ bias = (z == 0) ? Bu : ((z == 1) ? Br : Bc);
    float* __restrict__ C = g_XP[z];

    const int m0 = blockIdx.x * 128;
    const int n0 = blockIdx.y * 64;

    __shared__ __align__(16) float As[16][132];
    __shared__ __align__(16) float Bs[16][68];

    const int tid = threadIdx.x;
    const int tx  = tid & 15;
    const int ty  = tid >> 4;

    float acc[8][4];
#pragma unroll
    for (int i = 0; i < 8; i++)
#pragma unroll
        for (int j = 0; j < 4; j++) acc[i][j] = 0.f;

    for (int k0 = 0; k0 < HDIM; k0 += 16) {
#pragma unroll
        for (int i = 0; i < 2; i++) {
            int idx = tid * 2 + i;
            int row = idx >> 2;
            int c4  = idx & 3;
            float4 v = *reinterpret_cast<const float4*>(x + (size_t)(m0 + row) * HDIM + k0 + c4 * 4);
            As[c4 * 4 + 0][row] = v.x;
            As[c4 * 4 + 1][row] = v.y;
            As[c4 * 4 + 2][row] = v.z;
            As[c4 * 4 + 3][row] = v.w;
        }
        {
            int row = tid >> 2;
            int c4  = tid & 3;
            float4 v = *reinterpret_cast<const float4*>(Bmat + (size_t)(n0 + row) * HDIM + k0 + c4 * 4);
            Bs[c4 * 4 + 0][row] = v.x;
            Bs[c4 * 4 + 1][row] = v.y;
            Bs[c4 * 4 + 2][row] = v.z;
            Bs[c4 * 4 + 3][row] = v.w;
        }
        __syncthreads();

#pragma unroll
        for (int k = 0; k < 16; k++) {
            float a[8], b[4];
#pragma unroll
            for (int i = 0; i < 8; i++) a[i] = As[k][ty * 8 + i];
#pragma unroll
            for (int j = 0; j < 4; j++) b[j] = Bs[k][tx * 4 + j];
#pragma unroll
            for (int i = 0; i < 8; i++)
#pragma unroll
                for (int j = 0; j < 4; j++) acc[i][j] = fmaf(a[i], b[j], acc[i][j]);
        }
        __syncthreads();
    }

    float4 bv = *reinterpret_cast<const float4*>(bias + n0 + tx * 4);
#pragma unroll
    for (int i = 0; i < 8; i++) {
        float4 o;
        o.x = acc[i][0] + bv.x;
        o.y = acc[i][1] + bv.y;
        o.z = acc[i][2] + bv.z;
        o.w = acc[i][3] + bv.w;
        *reinterpret_cast<float4*>(C + (size_t)(m0 + ty * 8 + i) * HDIM + n0 + tx * 4) = o;
    }
}

// ---------------- Phase 2: persistent sequential scan (R2 sync skeleton) ----------------
__device__ __forceinline__ float sigmoidf_(float v) {
    return 1.f / (1.f + __expf(-v));
}
__device__ __forceinline__ u64 pack2(float lo, float hi) {
    u64 r;
    asm("mov.b64 %0, {%1, %2};" : "=l"(r) : "r"(__float_as_uint(lo)), "r"(__float_as_uint(hi)));
    return r;
}
__device__ __forceinline__ float sum2(u64 v) {
    unsigned lo, hi;
    asm("mov.b64 {%0, %1}, %2;" : "=r"(lo), "=r"(hi) : "l"(v));
    return __uint_as_float(lo) + __uint_as_float(hi);
}
__device__ __forceinline__ void ffma2(u64& d, u64 a, u64 b) {
    asm("fma.rn.f32x2 %0, %1, %2, %0;" : "+l"(d) : "l"(a), "l"(b));
}

__global__ __launch_bounds__(256, 1) void scan_kernel(
    const float* __restrict__ Wu, const float* __restrict__ Wr, const float* __restrict__ Wc,
    float* __restrict__ out)   // out[0:1024] = h_final, out[1024 + t*1024 + r] = outputs
{
    __shared__ __align__(16) float hs[HDIM];

    const int tid = threadIdx.x;
    const int l   = tid & 31;
    const int w   = tid >> 5;
    const int r   = blockIdx.x * 8 + w;      // this warp's hidden row

    // f32x2 layout: lane l owns column pairs c(j) = j*64 + 2l, j = 0..15.
    u64 wu2[16], wr2[16], wc2[16];
#pragma unroll
    for (int j = 0; j < 16; j++) {
        int c = j * 64 + 2 * l;
        float2 a = *reinterpret_cast<const float2*>(Wu + (size_t)r * HDIM + c);
        float2 b = *reinterpret_cast<const float2*>(Wr + (size_t)r * HDIM + c);
        float2 d = *reinterpret_cast<const float2*>(Wc + (size_t)r * HDIM + c);
        wu2[j] = pack2(a.x, a.y);
        wr2[j] = pack2(b.x, b.y);
        wc2[j] = pack2(d.x, d.y);
    }

    const float* __restrict__ XPu = g_XP[0];
    const float* __restrict__ XPr = g_XP[1];
    const float* __restrict__ XPc = g_XP[2];

    // Prologue: prefetch XP for t = 0 (lane 0 of each warp).
    float au = 0.f, ar = 0.f, ac = 0.f;
    if (l == 0) {
        au = __ldcg(XPu + r);
        ar = __ldcg(XPr + r);
        ac = __ldcg(XPc + r);
    }

    unsigned target = 0;

#pragma unroll 1
    for (int t = 0; t < T_SEQ; ++t) {
        const float* hin  = g_hbuf[t & 1];
        float*       hout = g_hbuf[(t + 1) & 1];

        // Stage h_t into shared memory (coalesced, L1-bypassing).
        float4 hv4 = __ldcg(reinterpret_cast<const float4*>(hin) + tid);
        reinterpret_cast<float4*>(hs)[tid] = hv4;
        __syncthreads();

        // Prefetch XP for the NEXT step now; DRAM latency hides under the dots.
        float aun = 0.f, arn = 0.f, acn = 0.f;
        if (l == 0) {
            int tn = (t + 1 < T_SEQ) ? (t + 1) : t;
            size_t off = (size_t)tn * HDIM + r;
            aun = __ldcg(XPu + off);
            arn = __ldcg(XPr + off);
            acn = __ldcg(XPc + off);
        }

        // Three dot products, packed f32x2 (exact fp32 pairwise FMA).
        u64 su2 = 0, sr2 = 0, sc2 = 0;
#pragma unroll
        for (int j = 0; j < 16; j++) {
            u64 hp = *reinterpret_cast<const u64*>(hs + j * 64 + 2 * l);
            ffma2(su2, wu2[j], hp);
            ffma2(sr2, wr2[j], hp);
            ffma2(sc2, wc2[j], hp);
        }
        float su = sum2(su2), sr = sum2(sr2), sc = sum2(sc2);
#pragma unroll
        for (int off = 16; off > 0; off >>= 1) {
            su += __shfl_down_sync(0xffffffffu, su, off);
            sr += __shfl_down_sync(0xffffffffu, sr, off);
            sc += __shfl_down_sync(0xffffffffu, sc, off);
        }

        if (l == 0) {
            float hprev = hs[r];
            float u  = sigmoidf_(au + su);
            float rg = sigmoidf_(ar + sr);
            float cd = sigmoidf_(ac + rg * sc);
            float hn = fmaf(u, hprev - cd, cd);   // u*h + (1-u)*cand
            __stcg(hout + r, hn);
            out[HDIM + (size_t)t * HDIM + r] = hn;
            if (t == T_SEQ - 1) out[r] = hn;
        }
        au = aun; ar = arn; ac = acn;

        // Grid-wide barrier (R2-proven: tid0 atomic counter + volatile poll).
        __syncthreads();
        if (tid == 0) {
            __threadfence();
            atomicAdd(&g_cnt, 1u);
            target += NBLK;
            while (*((volatile unsigned*)&g_cnt) < target) { }
            __threadfence();
        }
        __syncthreads();
    }
}

// ---------------- launch ----------------
extern "C" void kernel_launch(void* const* d_in, const int* in_sizes, int n_in,
                              void* d_out, int out_size) {
    const float* x  = (const float*)d_in[0];
    const float* Uu = (const float*)d_in[1];
    const float* Wu = (const float*)d_in[2];
    const float* Bu = (const float*)d_in[3];
    const float* Ur = (const float*)d_in[4];
    const float* Wr = (const float*)d_in[5];
    const float* Br = (const float*)d_in[6];
    const float* Uc = (const float*)d_in[7];
    const float* Wc = (const float*)d_in[8];
    const float* Bc = (const float*)d_in[9];
    float* out = (float*)d_out;

    reset_kernel<<<1, 256>>>();

    dim3 g(T_SEQ / 128, HDIM / 64, 3);
    proj_gemm<<<g, 256>>>(x, Uu, Ur, Uc, Bu, Br, Bc);

    scan_kernel<<<NBLK, 256>>>(Wu, Wr, Wc, out);
}